// round 6
// baseline (speedup 1.0000x reference)
#include <cuda_runtime.h>
#include <cuda_bf16.h>
#include <cstdint>
#include <math.h>

#define N_NODES 50000
#define N_EDGES 500000
#define D 128
#define TILE_M 128
#define N_TILES ((N_NODES + TILE_M - 1) / TILE_M)    // 391
#define SCAN_BLK 1024
#define N_SBLK ((N_NODES + SCAN_BLK - 1) / SCAN_BLK) // 49

// SMEM tile geometry (bf16, padded stride to kill ldmatrix bank conflicts)
#define TPAD 136
#define TILE_BYTES (128 * TPAD * 2)   // 34816
#define SM_AHI 0
#define SM_ALO (SM_AHI + TILE_BYTES)
#define SM_WHI (SM_ALO + TILE_BYTES)
#define SM_WLO (SM_WHI + TILE_BYTES)
#define SM_TOTAL (SM_WLO + TILE_BYTES)   // 139264

// ---------------- device scratch ----------------
__device__ int   g_is64;
__device__ int   g_src[N_EDGES];
__device__ int   g_dst[N_EDGES];
__device__ int   g_cnt[N_NODES];
__device__ int   g_cursor[N_NODES];
__device__ int   g_rowptr[N_NODES + 1];
__device__ int   g_csr_src[N_EDGES];
__device__ float g_csr_norm[N_EDGES];
__device__ float g_deg[N_NODES];
__device__ float g_dinv[N_NODES];
__device__ int   g_bsum[N_SBLK];
__device__ int   g_boff[N_SBLK];
__device__ float g_xw[(size_t)N_NODES * D];
__device__ __nv_bfloat16 g_ahi[(size_t)N_NODES * D];
__device__ __nv_bfloat16 g_alo[(size_t)N_NODES * D];
__device__ __nv_bfloat16 g_wthi[2][D * D];   // W^T (n-major, k contiguous)
__device__ __nv_bfloat16 g_wtlo[2][D * D];

// ================= helpers =================
__device__ __forceinline__ uint32_t smem_u32(const void* p) {
    uint32_t a;
    asm("{ .reg .u64 t; cvta.to.shared.u64 t, %1; cvt.u32.u64 %0, t; }"
        : "=r"(a) : "l"(p));
    return a;
}
__device__ __forceinline__ void ldsm_x4(uint32_t* r, uint32_t addr) {
    asm volatile("ldmatrix.sync.aligned.m8n8.x4.shared.b16 {%0,%1,%2,%3}, [%4];"
        : "=r"(r[0]), "=r"(r[1]), "=r"(r[2]), "=r"(r[3]) : "r"(addr));
}
__device__ __forceinline__ void mma16816(float* c, const uint32_t* a,
                                         uint32_t b0, uint32_t b1) {
    asm volatile(
        "mma.sync.aligned.m16n8k16.row.col.f32.bf16.bf16.f32 "
        "{%0,%1,%2,%3}, {%4,%5,%6,%7}, {%8,%9}, {%0,%1,%2,%3};"
        : "+f"(c[0]), "+f"(c[1]), "+f"(c[2]), "+f"(c[3])
        : "r"(a[0]), "r"(a[1]), "r"(a[2]), "r"(a[3]), "r"(b0), "r"(b1));
}
__device__ __forceinline__ uint32_t pack_hi2(float a, float b) {
    __nv_bfloat162 h(__float2bfloat16(a), __float2bfloat16(b));
    return *(uint32_t*)&h;
}
__device__ __forceinline__ uint32_t pack_lo2(float a, float b) {
    __nv_bfloat16 ha = __float2bfloat16(a), hb = __float2bfloat16(b);
    __nv_bfloat162 l(__float2bfloat16(a - __bfloat162float(ha)),
                     __float2bfloat16(b - __bfloat162float(hb)));
    return *(uint32_t*)&l;
}
__device__ __forceinline__ void fma4(float4& acc, const float4& v, float m) {
    acc.x = fmaf(v.x, m, acc.x);
    acc.y = fmaf(v.y, m, acc.y);
    acc.z = fmaf(v.z, m, acc.z);
    acc.w = fmaf(v.w, m, acc.w);
}

// ================= preprocessing =================
__global__ void detect_kernel(const unsigned int* __restrict__ w) {
    __shared__ unsigned int acc;
    int t = threadIdx.x;
    if (t == 0) acc = 0u;
    __syncthreads();
    unsigned int v = w[2 * t + 1];
    if (v) atomicOr(&acc, v);
    __syncthreads();
    if (t == 0) g_is64 = (acc == 0u) ? 1 : 0;
}

__global__ void init_kernel() {
    int i = blockIdx.x * blockDim.x + threadIdx.x;
    if (i < N_NODES) { g_deg[i] = 0.0f; g_cnt[i] = 0; }
}

__global__ void decode_kernel(const void* __restrict__ ei,
                              const float* __restrict__ ew) {
    int e = blockIdx.x * blockDim.x + threadIdx.x;
    if (e >= N_EDGES) return;
    int s, d;
    if (g_is64) {
        const long long* p = (const long long*)ei;
        s = (int)p[e]; d = (int)p[N_EDGES + e];
    } else {
        const int* p = (const int*)ei;
        s = p[e]; d = p[N_EDGES + e];
    }
    g_src[e] = s; g_dst[e] = d;
    atomicAdd(&g_deg[d], ew[e]);
    atomicAdd(&g_cnt[d], 1);
}

// --- hierarchical scan ---
__global__ void scan_reduce_kernel() {
    __shared__ int ws[32];
    int tid = threadIdx.x, lane = tid & 31, w = tid >> 5;
    int idx = blockIdx.x * SCAN_BLK + tid;
    int v = (idx < N_NODES) ? g_cnt[idx] : 0;
    #pragma unroll
    for (int o = 16; o > 0; o >>= 1) v += __shfl_xor_sync(0xFFFFFFFFu, v, o);
    if (lane == 0) ws[w] = v;
    __syncthreads();
    if (w == 0) {
        int sv = ws[lane];
        #pragma unroll
        for (int o = 16; o > 0; o >>= 1) sv += __shfl_xor_sync(0xFFFFFFFFu, sv, o);
        if (lane == 0) g_bsum[blockIdx.x] = sv;
    }
}

__global__ void scan_mid_kernel() {
    if (threadIdx.x == 0) {
        int run = 0;
        for (int i = 0; i < N_SBLK; i++) { g_boff[i] = run; run += g_bsum[i]; }
        g_rowptr[N_NODES] = run;
    }
}

// scan_final also computes dinv (deg is complete by now)
__global__ void scan_final_kernel() {
    __shared__ int ws[32];
    int tid = threadIdx.x, lane = tid & 31, w = tid >> 5;
    int idx = blockIdx.x * SCAN_BLK + tid;
    int v = (idx < N_NODES) ? g_cnt[idx] : 0;
    int x = v;
    #pragma unroll
    for (int o = 1; o < 32; o <<= 1) {
        int y = __shfl_up_sync(0xFFFFFFFFu, x, o);
        if (lane >= o) x += y;
    }
    if (lane == 31) ws[w] = x;
    __syncthreads();
    if (w == 0) {
        int sv = ws[lane];
        #pragma unroll
        for (int o = 1; o < 32; o <<= 1) {
            int y = __shfl_up_sync(0xFFFFFFFFu, sv, o);
            if (lane >= o) sv += y;
        }
        ws[lane] = sv;
    }
    __syncthreads();
    int excl = x - v + (w > 0 ? ws[w - 1] : 0) + g_boff[blockIdx.x];
    if (idx < N_NODES) {
        g_rowptr[idx] = excl;
        g_cursor[idx] = excl;
        g_dinv[idx] = rsqrtf(g_deg[idx] + 1.0f);
    }
}

__global__ void fill_kernel(const float* __restrict__ ew) {
    int e = blockIdx.x * blockDim.x + threadIdx.x;
    if (e >= N_EDGES) return;
    int s = g_src[e], d = g_dst[e];
    float nm = g_dinv[s] * ew[e] * g_dinv[d];
    int pos = atomicAdd(&g_cursor[d], 1);
    g_csr_src[pos] = s;
    g_csr_norm[pos] = nm;
}

// ================= weight split (tiny) =================
__global__ void split_w_kernel(const float* __restrict__ W, int which) {
    int i = blockIdx.x * blockDim.x + threadIdx.x;    // i = n*128 + k
    if (i >= D * D) return;
    int n = i >> 7, k = i & 127;
    float v = W[k * D + n];
    __nv_bfloat16 hi = __float2bfloat16(v);
    __nv_bfloat16 lo = __float2bfloat16(v - __bfloat162float(hi));
    g_wthi[which][i] = hi;
    g_wtlo[which][i] = lo;
}

// ================= HMMA GEMM =================
__device__ __forceinline__ void stage_tile(char* sm, int off,
                                           const __nv_bfloat16* __restrict__ src,
                                           int row0, int maxrow, int tid) {
    #pragma unroll
    for (int it = 0; it < 8; it++) {
        int c = it * 256 + tid;         // 2048 16B-chunks
        int r = c >> 4;
        int col8 = (c & 15) * 8;
        uint4 v = make_uint4(0, 0, 0, 0);
        if (row0 + r < maxrow)
            v = *(const uint4*)(src + (size_t)(row0 + r) * D + col8);
        *(uint4*)(sm + off + (r * TPAD + col8) * 2) = v;
    }
}

__device__ __forceinline__ void stage_x_split(char* sm,
                                              const float* __restrict__ src,
                                              int row0, int tid) {
    #pragma unroll
    for (int it = 0; it < 16; it++) {
        int c = it * 256 + tid;         // 4096 float4-chunks
        int r = c >> 5;
        int col4 = (c & 31) * 4;
        float4 v = make_float4(0.f, 0.f, 0.f, 0.f);
        if (row0 + r < N_NODES)
            v = *(const float4*)(src + (size_t)(row0 + r) * D + col4);
        uint2 hi, lo;
        hi.x = pack_hi2(v.x, v.y); hi.y = pack_hi2(v.z, v.w);
        lo.x = pack_lo2(v.x, v.y); lo.y = pack_lo2(v.z, v.w);
        *(uint2*)(sm + SM_AHI + (r * TPAD + col4) * 2) = hi;
        *(uint2*)(sm + SM_ALO + (r * TPAD + col4) * 2) = lo;
    }
}

__global__ __launch_bounds__(256, 1) void mma_gemm_kernel(const float* __restrict__ xsrc,
                                                          int use_x, int which) {
    extern __shared__ char smem[];
    uint32_t sbase = smem_u32(smem);
    int tid = threadIdx.x;
    int warp = tid >> 5, lane = tid & 31;
    int row0 = blockIdx.x * TILE_M;

    if (use_x) {
        stage_x_split(smem, xsrc, row0, tid);
    } else {
        stage_tile(smem, SM_AHI, g_ahi, row0, N_NODES, tid);
        stage_tile(smem, SM_ALO, g_alo, row0, N_NODES, tid);
    }
    stage_tile(smem, SM_WHI, g_wthi[which], 0, 128, tid);
    stage_tile(smem, SM_WLO, g_wtlo[which], 0, 128, tid);
    __syncthreads();

    int wm = warp >> 1;          // 0..3 : M group (32 rows)
    int wn = warp & 1;           // 0..1 : N group (64 cols)

    float acc[2][8][4];
    #pragma unroll
    for (int mi = 0; mi < 2; mi++)
        #pragma unroll
        for (int j = 0; j < 8; j++)
            #pragma unroll
            for (int q = 0; q < 4; q++) acc[mi][j][q] = 0.0f;

    int arow = (lane & 7) + ((lane >> 3) & 1) * 8;
    int acol = (lane >> 4) * 8;
    int brow = (lane & 7) + (lane >> 4) * 8;
    int bcol = ((lane >> 3) & 1) * 8;

    #pragma unroll
    for (int pass = 0; pass < 3; pass++) {
        int aoff = (pass == 2) ? SM_ALO : SM_AHI;
        int boff = (pass == 1) ? SM_WLO : SM_WHI;
        #pragma unroll
        for (int ks = 0; ks < 8; ks++) {
            uint32_t a[2][4];
            #pragma unroll
            for (int mi = 0; mi < 2; mi++) {
                uint32_t addr = sbase + aoff +
                    ((wm * 32 + mi * 16 + arow) * TPAD + ks * 16 + acol) * 2;
                ldsm_x4(a[mi], addr);
            }
            uint32_t b[4][4];
            #pragma unroll
            for (int j = 0; j < 4; j++) {
                uint32_t addr = sbase + boff +
                    ((wn * 64 + j * 16 + brow) * TPAD + ks * 16 + bcol) * 2;
                ldsm_x4(b[j], addr);
            }
            #pragma unroll
            for (int mi = 0; mi < 2; mi++)
                #pragma unroll
                for (int j = 0; j < 4; j++) {
                    mma16816(acc[mi][2 * j],     a[mi], b[j][0], b[j][1]);
                    mma16816(acc[mi][2 * j + 1], a[mi], b[j][2], b[j][3]);
                }
        }
    }

    int g = lane >> 2, cc = lane & 3;
    #pragma unroll
    for (int mi = 0; mi < 2; mi++) {
        int r_hi = row0 + wm * 32 + mi * 16 + g;
        #pragma unroll
        for (int j = 0; j < 8; j++) {
            int n0 = wn * 64 + j * 8 + 2 * cc;
            if (r_hi < N_NODES)
                *(float2*)(g_xw + (size_t)r_hi * D + n0) =
                    make_float2(acc[mi][j][0], acc[mi][j][1]);
            if (r_hi + 8 < N_NODES)
                *(float2*)(g_xw + (size_t)(r_hi + 8) * D + n0) =
                    make_float2(acc[mi][j][2], acc[mi][j][3]);
        }
    }
}

// ================= aggregation core (4-way unrolled gather) ================
__device__ __forceinline__ float4 gather_node(int n, int lane,
                                              const float* __restrict__ bias) {
    float di = g_dinv[n];
    float sl = di * di;
    float4 self = ((const float4*)(g_xw + (size_t)n * D))[lane];
    float4 bv = ((const float4*)bias)[lane];
    float4 acc;
    acc.x = fmaf(self.x, sl, bv.x);
    acc.y = fmaf(self.y, sl, bv.y);
    acc.z = fmaf(self.z, sl, bv.z);
    acc.w = fmaf(self.w, sl, bv.w);

    int k = g_rowptr[n], end = g_rowptr[n + 1];
    // 4-edge batches: 4 independent 512B row loads in flight (MLP=4)
    for (; k + 4 <= end; k += 4) {
        int s0 = g_csr_src[k], s1 = g_csr_src[k + 1];
        int s2 = g_csr_src[k + 2], s3 = g_csr_src[k + 3];
        float m0 = g_csr_norm[k], m1 = g_csr_norm[k + 1];
        float m2 = g_csr_norm[k + 2], m3 = g_csr_norm[k + 3];
        float4 v0 = *(const float4*)(g_xw + (size_t)s0 * D + lane * 4);
        float4 v1 = *(const float4*)(g_xw + (size_t)s1 * D + lane * 4);
        float4 v2 = *(const float4*)(g_xw + (size_t)s2 * D + lane * 4);
        float4 v3 = *(const float4*)(g_xw + (size_t)s3 * D + lane * 4);
        fma4(acc, v0, m0);
        fma4(acc, v1, m1);
        fma4(acc, v2, m2);
        fma4(acc, v3, m3);
    }
    for (; k < end; k++) {
        int s = g_csr_src[k];
        float nm = g_csr_norm[k];
        float4 v = *(const float4*)(g_xw + (size_t)s * D + lane * 4);
        fma4(acc, v, nm);
    }
    return acc;
}

// layer 1: emits bf16 hi/lo directly (gemm2 input)
__global__ __launch_bounds__(256) void agg_split_kernel(const float* __restrict__ bias) {
    int gwarp = (blockIdx.x * blockDim.x + threadIdx.x) >> 5;
    int lane = threadIdx.x & 31;
    if (gwarp >= N_NODES) return;
    float4 acc = gather_node(gwarp, lane, bias);
    uint2 hi, lo;
    hi.x = pack_hi2(acc.x, acc.y); hi.y = pack_hi2(acc.z, acc.w);
    lo.x = pack_lo2(acc.x, acc.y); lo.y = pack_lo2(acc.z, acc.w);
    *(uint2*)(g_ahi + (size_t)gwarp * D + lane * 4) = hi;
    *(uint2*)(g_alo + (size_t)gwarp * D + lane * 4) = lo;
}

// layer 2: fused with final head
__global__ __launch_bounds__(256) void agg_final_kernel(const float* __restrict__ bias,
                                                        const float* __restrict__ Wf,
                                                        const float* __restrict__ bf,
                                                        float* __restrict__ out) {
    int gwarp = (blockIdx.x * blockDim.x + threadIdx.x) >> 5;
    int lane = threadIdx.x & 31;
    if (gwarp >= N_NODES) return;
    float4 acc = gather_node(gwarp, lane, bias);
    float4 wv = ((const float4*)Wf)[lane];
    float d = acc.x * wv.x + acc.y * wv.y + acc.z * wv.z + acc.w * wv.w;
    #pragma unroll
    for (int o = 16; o > 0; o >>= 1)
        d += __shfl_xor_sync(0xFFFFFFFFu, d, o);
    if (lane == 0) {
        float z = d + bf[0];
        out[gwarp] = 10.0f / (1.0f + expf(-z));
    }
}

// ================= launcher =================
extern "C" void kernel_launch(void* const* d_in, const int* in_sizes, int n_in,
                              void* d_out, int out_size) {
    const float* x  = (const float*)d_in[0];
    const void*  ei = d_in[1];
    const float* ew = (const float*)d_in[2];
    const float* W1 = (const float*)d_in[3];
    const float* b1 = (const float*)d_in[4];
    const float* W2 = (const float*)d_in[5];
    const float* b2 = (const float*)d_in[6];
    const float* Wf = (const float*)d_in[7];
    const float* bf = (const float*)d_in[8];
    float* out = (float*)d_out;

    static cudaStream_t s_pre = nullptr;
    static cudaEvent_t ev_fork = nullptr, ev_join = nullptr;
    if (!s_pre) {
        cudaStreamCreateWithFlags(&s_pre, cudaStreamNonBlocking);
        cudaEventCreateWithFlags(&ev_fork, cudaEventDisableTiming);
        cudaEventCreateWithFlags(&ev_join, cudaEventDisableTiming);
        cudaFuncSetAttribute(mma_gemm_kernel,
                             cudaFuncAttributeMaxDynamicSharedMemorySize, SM_TOTAL);
    }

    const int NB = (N_NODES + 255) / 256;
    const int EB = (N_EDGES + 255) / 256;
    const int WB = (N_NODES * 32 + 255) / 256;

    // fork: preprocessing chain on side stream (independent of gemm1)
    cudaEventRecord(ev_fork, 0);
    cudaStreamWaitEvent(s_pre, ev_fork, 0);
    detect_kernel<<<1, 1024, 0, s_pre>>>((const unsigned int*)ei);
    init_kernel<<<NB, 256, 0, s_pre>>>();
    decode_kernel<<<EB, 256, 0, s_pre>>>(ei, ew);
    scan_reduce_kernel<<<N_SBLK, SCAN_BLK, 0, s_pre>>>();
    scan_mid_kernel<<<1, 32, 0, s_pre>>>();
    scan_final_kernel<<<N_SBLK, SCAN_BLK, 0, s_pre>>>();   // also computes dinv
    fill_kernel<<<EB, 256, 0, s_pre>>>(ew);
    cudaEventRecord(ev_join, s_pre);

    // main stream: weights + gemm1 (x staged+split in-kernel)
    split_w_kernel<<<(D * D + 255) / 256, 256>>>(W1, 0);
    split_w_kernel<<<(D * D + 255) / 256, 256>>>(W2, 1);
    mma_gemm_kernel<<<N_TILES, 256, SM_TOTAL>>>(x, 1, 0);

    // join: aggregation needs CSR
    cudaStreamWaitEvent(0, ev_join, 0);
    agg_split_kernel<<<WB, 256>>>(b1);                 // emits bf16 hi/lo
    mma_gemm_kernel<<<N_TILES, 256, SM_TOTAL>>>(nullptr, 0, 1);
    agg_final_kernel<<<WB, 256>>>(b2, Wf, bf, out);
}

// round 7
// speedup vs baseline: 1.2522x; 1.2522x over previous
#include <cuda_runtime.h>
#include <cuda_bf16.h>
#include <cstdint>
#include <math.h>

#define N_NODES 50000
#define N_EDGES 500000
#define D 128
#define SCAN_BLK 1024
#define N_SBLK ((N_NODES + SCAN_BLK - 1) / SCAN_BLK) // 49

// bf16 SMEM tile stride (padded to kill ldmatrix bank conflicts)
#define TPAD 136

// gemm1: 128-row tiles
#define T1_M 128
#define N_TILES1 ((N_NODES + T1_M - 1) / T1_M)       // 391
#define T1_BYTES (128 * TPAD * 2)                    // 34816
#define S1_AHI 0
#define S1_ALO (S1_AHI + T1_BYTES)
#define S1_WHI (S1_ALO + T1_BYTES)
#define S1_WLO (S1_WHI + T1_BYTES)
#define S1_TOTAL (S1_WLO + T1_BYTES)                 // 139264

// fused agg1+gemm2: 64-row tiles
#define T2_M 64
#define N_TILES2 ((N_NODES + T2_M - 1) / T2_M)       // 782
#define A2_BYTES (64 * TPAD * 2)                     // 17408
#define S2_AHI 0
#define S2_ALO (S2_AHI + A2_BYTES)
#define S2_WHI (S2_ALO + A2_BYTES)
#define S2_WLO (S2_WHI + T1_BYTES)
#define S2_TOTAL (S2_WLO + T1_BYTES)                 // 104448

// ---------------- device scratch ----------------
__device__ int   g_is64;
__device__ int   g_src[N_EDGES];
__device__ int   g_dst[N_EDGES];
__device__ int   g_cnt[N_NODES];
__device__ int   g_cursor[N_NODES];
__device__ int   g_rowptr[N_NODES + 1];
__device__ int   g_csr_src[N_EDGES];
__device__ float g_csr_norm[N_EDGES];
__device__ float g_deg[N_NODES];
__device__ float g_dinv[N_NODES];
__device__ int   g_bsum[N_SBLK];
__device__ int   g_boff[N_SBLK];
__device__ float g_xw[(size_t)N_NODES * D];    // gemm1 output (layer-1 messages)
__device__ float g_xw2[(size_t)N_NODES * D];   // gemm2 output (layer-2 messages)
__device__ __nv_bfloat16 g_wthi[2][D * D];     // W^T (n-major, k contiguous)
__device__ __nv_bfloat16 g_wtlo[2][D * D];

// ================= helpers =================
__device__ __forceinline__ uint32_t smem_u32(const void* p) {
    uint32_t a;
    asm("{ .reg .u64 t; cvta.to.shared.u64 t, %1; cvt.u32.u64 %0, t; }"
        : "=r"(a) : "l"(p));
    return a;
}
__device__ __forceinline__ void ldsm_x4(uint32_t* r, uint32_t addr) {
    asm volatile("ldmatrix.sync.aligned.m8n8.x4.shared.b16 {%0,%1,%2,%3}, [%4];"
        : "=r"(r[0]), "=r"(r[1]), "=r"(r[2]), "=r"(r[3]) : "r"(addr));
}
__device__ __forceinline__ void mma16816(float* c, const uint32_t* a,
                                         uint32_t b0, uint32_t b1) {
    asm volatile(
        "mma.sync.aligned.m16n8k16.row.col.f32.bf16.bf16.f32 "
        "{%0,%1,%2,%3}, {%4,%5,%6,%7}, {%8,%9}, {%0,%1,%2,%3};"
        : "+f"(c[0]), "+f"(c[1]), "+f"(c[2]), "+f"(c[3])
        : "r"(a[0]), "r"(a[1]), "r"(a[2]), "r"(a[3]), "r"(b0), "r"(b1));
}
__device__ __forceinline__ uint32_t pack_hi2(float a, float b) {
    __nv_bfloat162 h(__float2bfloat16(a), __float2bfloat16(b));
    return *(uint32_t*)&h;
}
__device__ __forceinline__ uint32_t pack_lo2(float a, float b) {
    __nv_bfloat16 ha = __float2bfloat16(a), hb = __float2bfloat16(b);
    __nv_bfloat162 l(__float2bfloat16(a - __bfloat162float(ha)),
                     __float2bfloat16(b - __bfloat162float(hb)));
    return *(uint32_t*)&l;
}
__device__ __forceinline__ void fma4(float4& acc, const float4& v, float m) {
    acc.x = fmaf(v.x, m, acc.x);
    acc.y = fmaf(v.y, m, acc.y);
    acc.z = fmaf(v.z, m, acc.z);
    acc.w = fmaf(v.w, m, acc.w);
}

// rolling 2-deep gather (R5 shape — do NOT batch, L1tex queue contention)
__device__ __forceinline__ float4 gather_node(const float* __restrict__ srcmat,
                                              int n, int lane,
                                              const float* __restrict__ bias) {
    float di = g_dinv[n];
    float sl = di * di;
    float4 self = ((const float4*)(srcmat + (size_t)n * D))[lane];
    float4 bv = ((const float4*)bias)[lane];
    float4 acc;
    acc.x = fmaf(self.x, sl, bv.x);
    acc.y = fmaf(self.y, sl, bv.y);
    acc.z = fmaf(self.z, sl, bv.z);
    acc.w = fmaf(self.w, sl, bv.w);
    int k = g_rowptr[n], end = g_rowptr[n + 1];
    if (k < end) {
        int s = g_csr_src[k];
        float nm = g_csr_norm[k];
        float4 v = *(const float4*)(srcmat + (size_t)s * D + lane * 4);
        for (k = k + 1; k < end; k++) {
            int s2 = g_csr_src[k];
            float nm2 = g_csr_norm[k];
            float4 v2 = *(const float4*)(srcmat + (size_t)s2 * D + lane * 4);
            fma4(acc, v, nm);
            v = v2; nm = nm2;
        }
        fma4(acc, v, nm);
    }
    return acc;
}

// ================= preprocessing =================
__global__ void detect_kernel(const unsigned int* __restrict__ w) {
    __shared__ unsigned int acc;
    int t = threadIdx.x;
    if (t == 0) acc = 0u;
    __syncthreads();
    unsigned int v = w[2 * t + 1];
    if (v) atomicOr(&acc, v);
    __syncthreads();
    if (t == 0) g_is64 = (acc == 0u) ? 1 : 0;
}

__global__ void init_kernel() {
    int i = blockIdx.x * blockDim.x + threadIdx.x;
    if (i < N_NODES) { g_deg[i] = 0.0f; g_cnt[i] = 0; }
}

__global__ void decode_kernel(const void* __restrict__ ei,
                              const float* __restrict__ ew) {
    int e = blockIdx.x * blockDim.x + threadIdx.x;
    if (e >= N_EDGES) return;
    int s, d;
    if (g_is64) {
        const long long* p = (const long long*)ei;
        s = (int)p[e]; d = (int)p[N_EDGES + e];
    } else {
        const int* p = (const int*)ei;
        s = p[e]; d = p[N_EDGES + e];
    }
    g_src[e] = s; g_dst[e] = d;
    atomicAdd(&g_deg[d], ew[e]);
    atomicAdd(&g_cnt[d], 1);
}

__global__ void scan_reduce_kernel() {
    __shared__ int ws[32];
    int tid = threadIdx.x, lane = tid & 31, w = tid >> 5;
    int idx = blockIdx.x * SCAN_BLK + tid;
    int v = (idx < N_NODES) ? g_cnt[idx] : 0;
    #pragma unroll
    for (int o = 16; o > 0; o >>= 1) v += __shfl_xor_sync(0xFFFFFFFFu, v, o);
    if (lane == 0) ws[w] = v;
    __syncthreads();
    if (w == 0) {
        int sv = ws[lane];
        #pragma unroll
        for (int o = 16; o > 0; o >>= 1) sv += __shfl_xor_sync(0xFFFFFFFFu, sv, o);
        if (lane == 0) g_bsum[blockIdx.x] = sv;
    }
}

__global__ void scan_mid_kernel() {
    if (threadIdx.x == 0) {
        int run = 0;
        for (int i = 0; i < N_SBLK; i++) { g_boff[i] = run; run += g_bsum[i]; }
        g_rowptr[N_NODES] = run;
    }
}

__global__ void scan_final_kernel() {
    __shared__ int ws[32];
    int tid = threadIdx.x, lane = tid & 31, w = tid >> 5;
    int idx = blockIdx.x * SCAN_BLK + tid;
    int v = (idx < N_NODES) ? g_cnt[idx] : 0;
    int x = v;
    #pragma unroll
    for (int o = 1; o < 32; o <<= 1) {
        int y = __shfl_up_sync(0xFFFFFFFFu, x, o);
        if (lane >= o) x += y;
    }
    if (lane == 31) ws[w] = x;
    __syncthreads();
    if (w == 0) {
        int sv = ws[lane];
        #pragma unroll
        for (int o = 1; o < 32; o <<= 1) {
            int y = __shfl_up_sync(0xFFFFFFFFu, sv, o);
            if (lane >= o) sv += y;
        }
        ws[lane] = sv;
    }
    __syncthreads();
    int excl = x - v + (w > 0 ? ws[w - 1] : 0) + g_boff[blockIdx.x];
    if (idx < N_NODES) {
        g_rowptr[idx] = excl;
        g_cursor[idx] = excl;
        g_dinv[idx] = rsqrtf(g_deg[idx] + 1.0f);
    }
}

__global__ void fill_kernel(const float* __restrict__ ew) {
    int e = blockIdx.x * blockDim.x + threadIdx.x;
    if (e >= N_EDGES) return;
    int s = g_src[e], d = g_dst[e];
    float nm = g_dinv[s] * ew[e] * g_dinv[d];
    int pos = atomicAdd(&g_cursor[d], 1);
    g_csr_src[pos] = s;
    g_csr_norm[pos] = nm;
}

__global__ void split_w_kernel(const float* __restrict__ W, int which) {
    int i = blockIdx.x * blockDim.x + threadIdx.x;    // i = n*128 + k
    if (i >= D * D) return;
    int n = i >> 7, k = i & 127;
    float v = W[k * D + n];
    __nv_bfloat16 hi = __float2bfloat16(v);
    __nv_bfloat16 lo = __float2bfloat16(v - __bfloat162float(hi));
    g_wthi[which][i] = hi;
    g_wtlo[which][i] = lo;
}

// ================= common staging =================
__device__ __forceinline__ void stage_w(char* sm, int off,
                                        const __nv_bfloat16* __restrict__ src,
                                        int tid) {
    #pragma unroll
    for (int it = 0; it < 8; it++) {
        int c = it * 256 + tid;         // 2048 16B-chunks (128 rows)
        int r = c >> 4;
        int col8 = (c & 15) * 8;
        uint4 v = *(const uint4*)(src + (size_t)r * D + col8);
        *(uint4*)(sm + off + (r * TPAD + col8) * 2) = v;
    }
}

// ================= gemm1: g_xw = split(x) @ W1 (128-row tiles) ============
__global__ __launch_bounds__(256, 1) void mma_gemm1_kernel(const float* __restrict__ xsrc) {
    extern __shared__ char smem[];
    uint32_t sbase = smem_u32(smem);
    int tid = threadIdx.x;
    int warp = tid >> 5, lane = tid & 31;
    int row0 = blockIdx.x * T1_M;

    // stage x, splitting to hi/lo on the fly
    #pragma unroll
    for (int it = 0; it < 16; it++) {
        int c = it * 256 + tid;         // 4096 float4-chunks
        int r = c >> 5;
        int col4 = (c & 31) * 4;
        float4 v = make_float4(0.f, 0.f, 0.f, 0.f);
        if (row0 + r < N_NODES)
            v = *(const float4*)(xsrc + (size_t)(row0 + r) * D + col4);
        uint2 hi, lo;
        hi.x = pack_hi2(v.x, v.y); hi.y = pack_hi2(v.z, v.w);
        lo.x = pack_lo2(v.x, v.y); lo.y = pack_lo2(v.z, v.w);
        *(uint2*)(smem + S1_AHI + (r * TPAD + col4) * 2) = hi;
        *(uint2*)(smem + S1_ALO + (r * TPAD + col4) * 2) = lo;
    }
    stage_w(smem, S1_WHI, g_wthi[0], tid);
    stage_w(smem, S1_WLO, g_wtlo[0], tid);
    __syncthreads();

    int wm = warp >> 1;          // 0..3 : M group (32 rows)
    int wn = warp & 1;           // 0..1 : N group (64 cols)

    float acc[2][8][4];
    #pragma unroll
    for (int mi = 0; mi < 2; mi++)
        #pragma unroll
        for (int j = 0; j < 8; j++)
            #pragma unroll
            for (int q = 0; q < 4; q++) acc[mi][j][q] = 0.0f;

    int arow = (lane & 7) + ((lane >> 3) & 1) * 8;
    int acol = (lane >> 4) * 8;
    int brow = (lane & 7) + (lane >> 4) * 8;
    int bcol = ((lane >> 3) & 1) * 8;

    #pragma unroll
    for (int pass = 0; pass < 3; pass++) {
        int aoff = (pass == 2) ? S1_ALO : S1_AHI;
        int boff = (pass == 1) ? S1_WLO : S1_WHI;
        #pragma unroll
        for (int ks = 0; ks < 8; ks++) {
            uint32_t a[2][4];
            #pragma unroll
            for (int mi = 0; mi < 2; mi++)
                ldsm_x4(a[mi], sbase + aoff +
                    ((wm * 32 + mi * 16 + arow) * TPAD + ks * 16 + acol) * 2);
            uint32_t b[4][4];
            #pragma unroll
            for (int j = 0; j < 4; j++)
                ldsm_x4(b[j], sbase + boff +
                    ((wn * 64 + j * 16 + brow) * TPAD + ks * 16 + bcol) * 2);
            #pragma unroll
            for (int mi = 0; mi < 2; mi++)
                #pragma unroll
                for (int j = 0; j < 4; j++) {
                    mma16816(acc[mi][2 * j],     a[mi], b[j][0], b[j][1]);
                    mma16816(acc[mi][2 * j + 1], a[mi], b[j][2], b[j][3]);
                }
        }
    }

    int g = lane >> 2, cc = lane & 3;
    #pragma unroll
    for (int mi = 0; mi < 2; mi++) {
        int r_hi = row0 + wm * 32 + mi * 16 + g;
        #pragma unroll
        for (int j = 0; j < 8; j++) {
            int n0 = wn * 64 + j * 8 + 2 * cc;
            if (r_hi < N_NODES)
                *(float2*)(g_xw + (size_t)r_hi * D + n0) =
                    make_float2(acc[mi][j][0], acc[mi][j][1]);
            if (r_hi + 8 < N_NODES)
                *(float2*)(g_xw + (size_t)(r_hi + 8) * D + n0) =
                    make_float2(acc[mi][j][2], acc[mi][j][3]);
        }
    }
}

// ========== fused agg1 + gemm2: g_xw2 = split(agg(g_xw)+b1) @ W2 ==========
// 64-row tiles; gather results go registers -> SMEM MMA tiles (no gmem trip).
__global__ __launch_bounds__(256, 2) void fused_agg_gemm2_kernel(const float* __restrict__ b1) {
    extern __shared__ char smem[];
    uint32_t sbase = smem_u32(smem);
    int tid = threadIdx.x;
    int warp = tid >> 5, lane = tid & 31;
    int row0 = blockIdx.x * T2_M;

    stage_w(smem, S2_WHI, g_wthi[1], tid);
    stage_w(smem, S2_WLO, g_wtlo[1], tid);

    // gather 64 rows: warp w handles local rows w*8 .. w*8+7
    #pragma unroll 1
    for (int i = 0; i < 8; i++) {
        int nl = warp * 8 + i;
        int n = row0 + nl;
        uint2 hi = make_uint2(0, 0), lo = make_uint2(0, 0);
        if (n < N_NODES) {
            float4 acc = gather_node(g_xw, n, lane, b1);
            hi.x = pack_hi2(acc.x, acc.y); hi.y = pack_hi2(acc.z, acc.w);
            lo.x = pack_lo2(acc.x, acc.y); lo.y = pack_lo2(acc.z, acc.w);
        }
        *(uint2*)(smem + S2_AHI + (nl * TPAD + lane * 4) * 2) = hi;
        *(uint2*)(smem + S2_ALO + (nl * TPAD + lane * 4) * 2) = lo;
    }
    __syncthreads();

    int wm = warp & 1;           // 0..1 : M group (32 rows)
    int wn = warp >> 1;          // 0..3 : N group (32 cols)

    float acc[2][4][4];
    #pragma unroll
    for (int mi = 0; mi < 2; mi++)
        #pragma unroll
        for (int j = 0; j < 4; j++)
            #pragma unroll
            for (int q = 0; q < 4; q++) acc[mi][j][q] = 0.0f;

    int arow = (lane & 7) + ((lane >> 3) & 1) * 8;
    int acol = (lane >> 4) * 8;
    int brow = (lane & 7) + (lane >> 4) * 8;
    int bcol = ((lane >> 3) & 1) * 8;

    #pragma unroll
    for (int pass = 0; pass < 3; pass++) {
        int aoff = (pass == 2) ? S2_ALO : S2_AHI;
        int boff = (pass == 1) ? S2_WLO : S2_WHI;
        #pragma unroll
        for (int ks = 0; ks < 8; ks++) {
            uint32_t a[2][4];
            #pragma unroll
            for (int mi = 0; mi < 2; mi++)
                ldsm_x4(a[mi], sbase + aoff +
                    ((wm * 32 + mi * 16 + arow) * TPAD + ks * 16 + acol) * 2);
            uint32_t b[2][4];
            #pragma unroll
            for (int jj = 0; jj < 2; jj++)
                ldsm_x4(b[jj], sbase + boff +
                    ((wn * 32 + jj * 16 + brow) * TPAD + ks * 16 + bcol) * 2);
            #pragma unroll
            for (int mi = 0; mi < 2; mi++)
                #pragma unroll
                for (int jj = 0; jj < 2; jj++) {
                    mma16816(acc[mi][2 * jj],     a[mi], b[jj][0], b[jj][1]);
                    mma16816(acc[mi][2 * jj + 1], a[mi], b[jj][2], b[jj][3]);
                }
        }
    }

    int g = lane >> 2, cc = lane & 3;
    #pragma unroll
    for (int mi = 0; mi < 2; mi++) {
        int r_hi = row0 + wm * 32 + mi * 16 + g;
        #pragma unroll
        for (int j = 0; j < 4; j++) {
            int n0 = wn * 32 + j * 8 + 2 * cc;
            if (r_hi < N_NODES)
                *(float2*)(g_xw2 + (size_t)r_hi * D + n0) =
                    make_float2(acc[mi][j][0], acc[mi][j][1]);
            if (r_hi + 8 < N_NODES)
                *(float2*)(g_xw2 + (size_t)(r_hi + 8) * D + n0) =
                    make_float2(acc[mi][j][2], acc[mi][j][3]);
        }
    }
}

// ================= layer-2 agg fused with final head ======================
__global__ __launch_bounds__(256) void agg_final_kernel(const float* __restrict__ bias,
                                                        const float* __restrict__ Wf,
                                                        const float* __restrict__ bf,
                                                        float* __restrict__ out) {
    int gwarp = (blockIdx.x * blockDim.x + threadIdx.x) >> 5;
    int lane = threadIdx.x & 31;
    if (gwarp >= N_NODES) return;
    float4 acc = gather_node(g_xw2, gwarp, lane, bias);
    float4 wv = ((const float4*)Wf)[lane];
    float d = acc.x * wv.x + acc.y * wv.y + acc.z * wv.z + acc.w * wv.w;
    #pragma unroll
    for (int o = 16; o > 0; o >>= 1)
        d += __shfl_xor_sync(0xFFFFFFFFu, d, o);
    if (lane == 0) {
        float z = d + bf[0];
        out[gwarp] = 10.0f / (1.0f + expf(-z));
    }
}

// ================= launcher =================
extern "C" void kernel_launch(void* const* d_in, const int* in_sizes, int n_in,
                              void* d_out, int out_size) {
    const float* x  = (const float*)d_in[0];
    const void*  ei = d_in[1];
    const float* ew = (const float*)d_in[2];
    const float* W1 = (const float*)d_in[3];
    const float* b1 = (const float*)d_in[4];
    const float* W2 = (const float*)d_in[5];
    const float* b2 = (const float*)d_in[6];
    const float* Wf = (const float*)d_in[7];
    const float* bf = (const float*)d_in[8];
    float* out = (float*)d_out;

    static cudaStream_t s_pre = nullptr;
    static cudaEvent_t ev_fork = nullptr, ev_join = nullptr;
    if (!s_pre) {
        cudaStreamCreateWithFlags(&s_pre, cudaStreamNonBlocking);
        cudaEventCreateWithFlags(&ev_fork, cudaEventDisableTiming);
        cudaEventCreateWithFlags(&ev_join, cudaEventDisableTiming);
        cudaFuncSetAttribute(mma_gemm1_kernel,
                             cudaFuncAttributeMaxDynamicSharedMemorySize, S1_TOTAL);
        cudaFuncSetAttribute(fused_agg_gemm2_kernel,
                             cudaFuncAttributeMaxDynamicSharedMemorySize, S2_TOTAL);
    }

    const int NB = (N_NODES + 255) / 256;
    const int EB = (N_EDGES + 255) / 256;
    const int WB = (N_NODES * 32 + 255) / 256;

    // fork: preprocessing chain on side stream (independent of gemm1)
    cudaEventRecord(ev_fork, 0);
    cudaStreamWaitEvent(s_pre, ev_fork, 0);
    detect_kernel<<<1, 1024, 0, s_pre>>>((const unsigned int*)ei);
    init_kernel<<<NB, 256, 0, s_pre>>>();
    decode_kernel<<<EB, 256, 0, s_pre>>>(ei, ew);
    scan_reduce_kernel<<<N_SBLK, SCAN_BLK, 0, s_pre>>>();
    scan_mid_kernel<<<1, 32, 0, s_pre>>>();
    scan_final_kernel<<<N_SBLK, SCAN_BLK, 0, s_pre>>>();   // also computes dinv
    fill_kernel<<<EB, 256, 0, s_pre>>>(ew);
    cudaEventRecord(ev_join, s_pre);

    // main stream: weights + gemm1 (x staged+split in-kernel)
    split_w_kernel<<<(D * D + 255) / 256, 256>>>(W1, 0);
    split_w_kernel<<<(D * D + 255) / 256, 256>>>(W2, 1);
    mma_gemm1_kernel<<<N_TILES1, 256, S1_TOTAL>>>(x);

    // join: aggregation needs CSR
    cudaStreamWaitEvent(0, ev_join, 0);
    fused_agg_gemm2_kernel<<<N_TILES2, 256, S2_TOTAL>>>(b1);
    agg_final_kernel<<<WB, 256>>>(b2, Wf, bf, out);
}

// round 8
// speedup vs baseline: 2.8540x; 2.2791x over previous
#include <cuda_runtime.h>
#include <cuda_bf16.h>
#include <cstdint>
#include <math.h>

#define N_NODES 50000
#define N_EDGES 500000
#define D 128

// ---------------- device scratch ----------------
__device__ int   g_is64;
__device__ int   g_src[N_EDGES];
__device__ int   g_dst[N_EDGES];
__device__ float g_deg[N_NODES];
__device__ float g_dinv[N_NODES];
__device__ float g_w[D];        // w = W1 @ W2 @ Wf
__device__ float g_c1;          // b1 . (W2 @ Wf)
__device__ float g_c2;          // b2 . Wf + bf
__device__ float g_y0[N_NODES]; // X @ w
__device__ float g_t1[N_NODES]; // Anorm(y0)
__device__ float g_u[N_NODES];  // Anorm(1)
__device__ float g_t2[N_NODES]; // Anorm(t1)

// ================= preprocessing =================
// edge_index stored as int64 (odd 32-bit words all zero) or int32?
__global__ void detect_kernel(const unsigned int* __restrict__ w) {
    __shared__ unsigned int acc;
    int t = threadIdx.x;
    if (t == 0) acc = 0u;
    __syncthreads();
    unsigned int v = w[2 * t + 1];
    if (v) atomicOr(&acc, v);
    __syncthreads();
    if (t == 0) g_is64 = (acc == 0u) ? 1 : 0;
}

__global__ void zero_deg_kernel() {
    int i = blockIdx.x * blockDim.x + threadIdx.x;
    if (i < N_NODES) g_deg[i] = 0.0f;
}

__global__ void decode_kernel(const void* __restrict__ ei,
                              const float* __restrict__ ew) {
    int e = blockIdx.x * blockDim.x + threadIdx.x;
    if (e >= N_EDGES) return;
    int s, d;
    if (g_is64) {
        const long long* p = (const long long*)ei;
        s = (int)p[e]; d = (int)p[N_EDGES + e];
    } else {
        const int* p = (const int*)ei;
        s = p[e]; d = p[N_EDGES + e];
    }
    g_src[e] = s; g_dst[e] = d;
    atomicAdd(&g_deg[d], ew[e]);
}

__global__ void dinv_kernel() {
    int i = blockIdx.x * blockDim.x + threadIdx.x;
    if (i < N_NODES) g_dinv[i] = rsqrtf(g_deg[i] + 1.0f);
}

// ================= collapsed weights: w = W1 W2 Wf, c1, c2 ================
__global__ void wvec_kernel(const float* __restrict__ W1,
                            const float* __restrict__ b1,
                            const float* __restrict__ W2,
                            const float* __restrict__ b2,
                            const float* __restrict__ Wf,
                            const float* __restrict__ bf) {
    __shared__ float sWf[D], sv2[D];
    int t = threadIdx.x;                 // 128 threads
    sWf[t] = Wf[t];
    __syncthreads();
    float a = 0.0f;
    #pragma unroll 8
    for (int j = 0; j < D; j++) a += W2[t * D + j] * sWf[j];
    sv2[t] = a;                          // v2 = W2 @ Wf
    __syncthreads();
    float wv = 0.0f;
    #pragma unroll 8
    for (int k = 0; k < D; k++) wv += W1[t * D + k] * sv2[k];
    g_w[t] = wv;                         // w = W1 @ v2
    if (t == 0) {
        float c1 = 0.0f, c2 = 0.0f;
        for (int k = 0; k < D; k++) c1 += b1[k] * sv2[k];
        for (int j = 0; j < D; j++) c2 += b2[j] * sWf[j];
        g_c1 = c1;
        g_c2 = c2 + bf[0];
    }
}

// ================= GEMV: y0 = X @ w (warp per node) =======================
__global__ __launch_bounds__(256) void gemv_kernel(const float* __restrict__ x) {
    int gwarp = (blockIdx.x * blockDim.x + threadIdx.x) >> 5;
    int lane = threadIdx.x & 31;
    if (gwarp >= N_NODES) return;
    float4 xv = *(const float4*)(x + (size_t)gwarp * D + lane * 4);
    float4 wv = *(const float4*)(g_w + lane * 4);
    float d = xv.x * wv.x + xv.y * wv.y + xv.z * wv.z + xv.w * wv.w;
    #pragma unroll
    for (int o = 16; o > 0; o >>= 1)
        d += __shfl_xor_sync(0xFFFFFFFFu, d, o);
    if (lane == 0) g_y0[gwarp] = d;
}

// ================= scalar aggregation passes ===============================
// self terms (assignment = also initializes the accumulators)
__global__ void self1_kernel() {
    int n = blockIdx.x * blockDim.x + threadIdx.x;
    if (n >= N_NODES) return;
    float di = g_dinv[n];
    float sl = di * di;
    g_t1[n] = sl * g_y0[n];
    g_u[n]  = sl;
}

__global__ void edge1_kernel(const float* __restrict__ ew) {
    int e = blockIdx.x * blockDim.x + threadIdx.x;
    if (e >= N_EDGES) return;
    int s = g_src[e], d = g_dst[e];
    float nm = g_dinv[s] * ew[e] * g_dinv[d];
    atomicAdd(&g_t1[d], nm * g_y0[s]);
    atomicAdd(&g_u[d], nm);
}

__global__ void self2_kernel() {
    int n = blockIdx.x * blockDim.x + threadIdx.x;
    if (n >= N_NODES) return;
    float di = g_dinv[n];
    g_t2[n] = di * di * g_t1[n];
}

__global__ void edge2_kernel(const float* __restrict__ ew) {
    int e = blockIdx.x * blockDim.x + threadIdx.x;
    if (e >= N_EDGES) return;
    int s = g_src[e], d = g_dst[e];
    float nm = g_dinv[s] * ew[e] * g_dinv[d];
    atomicAdd(&g_t2[d], nm * g_t1[s]);
}

__global__ void final_kernel(float* __restrict__ out) {
    int n = blockIdx.x * blockDim.x + threadIdx.x;
    if (n >= N_NODES) return;
    float z = g_t2[n] + g_c1 * g_u[n] + g_c2;
    out[n] = 10.0f / (1.0f + expf(-z));
}

// ================= launcher =================
extern "C" void kernel_launch(void* const* d_in, const int* in_sizes, int n_in,
                              void* d_out, int out_size) {
    const float* x  = (const float*)d_in[0];
    const void*  ei = d_in[1];
    const float* ew = (const float*)d_in[2];
    const float* W1 = (const float*)d_in[3];
    const float* b1 = (const float*)d_in[4];
    const float* W2 = (const float*)d_in[5];
    const float* b2 = (const float*)d_in[6];
    const float* Wf = (const float*)d_in[7];
    const float* bf = (const float*)d_in[8];
    float* out = (float*)d_out;

    static cudaStream_t s_pre = nullptr;
    static cudaEvent_t ev_fork = nullptr, ev_join = nullptr;
    if (!s_pre) {
        cudaStreamCreateWithFlags(&s_pre, cudaStreamNonBlocking);
        cudaEventCreateWithFlags(&ev_fork, cudaEventDisableTiming);
        cudaEventCreateWithFlags(&ev_join, cudaEventDisableTiming);
    }

    const int NB = (N_NODES + 255) / 256;
    const int EB = (N_EDGES + 255) / 256;
    const int GB = (N_NODES * 32 + 255) / 256;   // warp-per-node gemv

    // fork: edge preprocessing on side stream
    cudaEventRecord(ev_fork, 0);
    cudaStreamWaitEvent(s_pre, ev_fork, 0);
    detect_kernel<<<1, 1024, 0, s_pre>>>((const unsigned int*)ei);
    zero_deg_kernel<<<NB, 256, 0, s_pre>>>();
    decode_kernel<<<EB, 256, 0, s_pre>>>(ei, ew);
    dinv_kernel<<<NB, 256, 0, s_pre>>>();
    cudaEventRecord(ev_join, s_pre);

    // main: collapsed weight vector + GEMV (independent of edges)
    wvec_kernel<<<1, 128>>>(W1, b1, W2, b2, Wf, bf);
    gemv_kernel<<<GB, 256>>>(x);

    // join, then two scalar Anorm applications + head
    cudaStreamWaitEvent(0, ev_join, 0);
    self1_kernel<<<NB, 256>>>();
    edge1_kernel<<<EB, 256>>>(ew);
    self2_kernel<<<NB, 256>>>();
    edge2_kernel<<<EB, 256>>>(ew);
    final_kernel<<<NB, 256>>>(out);
}

// round 9
// speedup vs baseline: 3.0618x; 1.0728x over previous
#include <cuda_runtime.h>
#include <cstdint>
#include <math.h>

#define N_NODES 50000
#define N_EDGES 500000
#define D 128
#define NBLK 148
#define NTHR 1024
#define NTOT (NBLK * NTHR)          // 151552 threads
#define EPT 4                        // max edges per thread (ceil(500000/151552))

// ---------------- device state ----------------
__device__ int   g_is64;
__device__ int   g_barc[4];
__device__ float g_deg[N_NODES];
__device__ float g_w[D];            // w = W1 @ W2 @ Wf
__device__ float g_c1;              // b1 . (W2 @ Wf)
__device__ float g_c2;              // b2 . Wf + bf
__device__ float g_y0[N_NODES];     // X @ w
__device__ float g_t1e[N_NODES];    // edge part of Anorm(y0)
__device__ float g_ue[N_NODES];     // edge part of Anorm(1)
__device__ float g_t2e[N_NODES];    // edge part of Anorm(t1)

// reset barrier counters each replay (stream-ordered before fused kernel)
__global__ void reset_kernel() {
    if (threadIdx.x < 4) g_barc[threadIdx.x] = 0;
}

// grid-wide barrier: fenced arrive + L2 atomic poll
__device__ __forceinline__ void gbar(int i) {
    __syncthreads();
    if (threadIdx.x == 0) {
        __threadfence();
        atomicAdd(&g_barc[i], 1);
        while (atomicAdd(&g_barc[i], 0) < NBLK) { }
        __threadfence();
    }
    __syncthreads();
}

__global__ __launch_bounds__(NTHR, 1) void fused_kernel(
    const float* __restrict__ x,  const void* __restrict__ ei,
    const float* __restrict__ ew,
    const float* __restrict__ W1, const float* __restrict__ b1,
    const float* __restrict__ W2, const float* __restrict__ b2,
    const float* __restrict__ Wf, const float* __restrict__ bf,
    float* __restrict__ out)
{
    __shared__ unsigned int s_acc;
    __shared__ float sWf[D], sv2[D];

    const int tid = threadIdx.x;
    const int gt  = blockIdx.x * NTHR + tid;

    // ================= P0: zero accumulators, detect dtype, collapse weights
    for (int i = gt; i < N_NODES; i += NTOT) {
        g_deg[i] = 0.0f; g_t1e[i] = 0.0f; g_ue[i] = 0.0f; g_t2e[i] = 0.0f;
    }
    if (blockIdx.x == 0) {
        // int64 edge_index => odd 32-bit words of first 1024 values are all 0
        if (tid == 0) s_acc = 0u;
        __syncthreads();
        unsigned int v = ((const unsigned int*)ei)[2 * tid + 1];
        if (v) atomicOr(&s_acc, v);
        __syncthreads();
        if (tid == 0) g_is64 = (s_acc == 0u) ? 1 : 0;
    }
    if (blockIdx.x == 1) {
        if (tid < D) sWf[tid] = Wf[tid];
        __syncthreads();
        if (tid < D) {
            float a = 0.0f;
            #pragma unroll 8
            for (int j = 0; j < D; j++) a += W2[tid * D + j] * sWf[j];
            sv2[tid] = a;                       // v2 = W2 @ Wf
        }
        __syncthreads();
        if (tid < D) {
            float wv = 0.0f;
            #pragma unroll 8
            for (int k = 0; k < D; k++) wv += W1[tid * D + k] * sv2[k];
            g_w[tid] = wv;                      // w = W1 @ v2
        }
        if (tid == 0) {
            float c1 = 0.0f, c2 = 0.0f;
            for (int k = 0; k < D; k++) c1 += b1[k] * sv2[k];
            for (int j = 0; j < D; j++) c2 += b2[j] * sWf[j];
            g_c1 = c1;
            g_c2 = c2 + bf[0];
        }
    }
    gbar(0);

    // ================= P1: gemv y0 = X @ w  +  decode edges + deg atomics
    {
        int gwarp = gt >> 5, lane = gt & 31;
        float4 wv4 = __ldcg((const float4*)g_w + lane);
        for (int n = gwarp; n < N_NODES; n += NTOT / 32) {
            float4 xv = *(const float4*)(x + (size_t)n * D + lane * 4);
            float d = xv.x * wv4.x + xv.y * wv4.y + xv.z * wv4.z + xv.w * wv4.w;
            #pragma unroll
            for (int o = 16; o > 0; o >>= 1)
                d += __shfl_xor_sync(0xFFFFFFFFu, d, o);
            if (lane == 0) g_y0[n] = d;
        }
    }
    int es[EPT], ed[EPT];
    float eev[EPT];
    {
        int is64 = __ldcg(&g_is64);
        #pragma unroll
        for (int i = 0; i < EPT; i++) {
            int e = gt + i * NTOT;
            es[i] = 0; ed[i] = 0; eev[i] = 0.0f;
            if (e < N_EDGES) {
                int s, d;
                if (is64) {
                    const long long* p = (const long long*)ei;
                    s = (int)p[e]; d = (int)p[N_EDGES + e];
                } else {
                    const int* p = (const int*)ei;
                    s = p[e]; d = p[N_EDGES + e];
                }
                float w = ew[e];
                es[i] = s; ed[i] = d; eev[i] = w;
                atomicAdd(&g_deg[d], w);
            }
        }
    }
    gbar(1);

    // ================= P2: edge pass 1 — t1e[d] += nm*y0[s], ue[d] += nm
    float enm[EPT], edy[EPT];
    #pragma unroll
    for (int i = 0; i < EPT; i++) {
        int e = gt + i * NTOT;
        enm[i] = 0.0f; edy[i] = 0.0f;
        if (e < N_EDGES) {
            int s = es[i], d = ed[i];
            float dis = rsqrtf(__ldcg(&g_deg[s]) + 1.0f);
            float did = rsqrtf(__ldcg(&g_deg[d]) + 1.0f);
            float nm  = dis * eev[i] * did;
            float y0s = __ldcg(&g_y0[s]);
            enm[i] = nm;
            edy[i] = dis * dis * y0s;           // self part of t1_full[s]
            atomicAdd(&g_t1e[d], nm * y0s);
            atomicAdd(&g_ue[d], nm);
        }
    }
    gbar(2);

    // ================= P3: edge pass 2 — t2e[d] += nm * t1_full[s]
    #pragma unroll
    for (int i = 0; i < EPT; i++) {
        int e = gt + i * NTOT;
        if (e < N_EDGES) {
            float t1fs = edy[i] + __ldcg(&g_t1e[es[i]]);
            atomicAdd(&g_t2e[ed[i]], enm[i] * t1fs);
        }
    }
    gbar(3);

    // ================= P4: final head
    {
        float c1 = __ldcg(&g_c1), c2 = __ldcg(&g_c2);
        for (int n = gt; n < N_NODES; n += NTOT) {
            float di  = rsqrtf(__ldcg(&g_deg[n]) + 1.0f);
            float sl  = di * di;
            float y0  = __ldcg(&g_y0[n]);
            float t1f = sl * y0 + __ldcg(&g_t1e[n]);
            float uf  = sl + __ldcg(&g_ue[n]);
            float z   = sl * t1f + __ldcg(&g_t2e[n]) + c1 * uf + c2;
            out[n] = 10.0f / (1.0f + expf(-z));
        }
    }
}

// ================= launcher =================
extern "C" void kernel_launch(void* const* d_in, const int* in_sizes, int n_in,
                              void* d_out, int out_size) {
    const float* x  = (const float*)d_in[0];
    const void*  ei = d_in[1];
    const float* ew = (const float*)d_in[2];
    const float* W1 = (const float*)d_in[3];
    const float* b1 = (const float*)d_in[4];
    const float* W2 = (const float*)d_in[5];
    const float* b2 = (const float*)d_in[6];
    const float* Wf = (const float*)d_in[7];
    const float* bf = (const float*)d_in[8];
    float* out = (float*)d_out;

    reset_kernel<<<1, 32>>>();
    fused_kernel<<<NBLK, NTHR>>>(x, ei, ew, W1, b1, W2, b2, Wf, bf, out);
}

// round 10
// speedup vs baseline: 4.3276x; 1.4134x over previous
#include <cuda_runtime.h>
#include <cstdint>
#include <math.h>

#define N_NODES 50000
#define N_EDGES 500000
#define D 128
#define NBLK 148
#define NTHR 1024
#define NTOT (NBLK * NTHR)          // 151552 threads
#define NW   (NTOT / 32)            // 4736 warps
#define EPT 4                        // max edges per thread

// ---------------- device state ----------------
__device__ int   g_is64;
__device__ int   g_barc[8];
__device__ float g_deg[N_NODES];
__device__ float g_v2[D];           // W2 @ Wf
__device__ float g_w[D];            // W1 @ v2
__device__ float g_c1;              // b1 . v2
__device__ float g_c2;              // b2 . Wf + bf
__device__ float g_y0[N_NODES];     // X @ w
__device__ float g_t1e[N_NODES];    // edge part of Anorm(y0)
__device__ float g_ue[N_NODES];     // edge part of Anorm(1)
__device__ float g_t2e[N_NODES];    // edge part of Anorm(t1)

__global__ void reset_kernel() {
    if (threadIdx.x < 8) g_barc[threadIdx.x] = 0;
}

// grid-wide barrier: fenced arrive + gentle L2 atomic poll
__device__ __forceinline__ void gbar(int i) {
    __syncthreads();
    if (threadIdx.x == 0) {
        __threadfence();
        atomicAdd(&g_barc[i], 1);
        while (atomicAdd(&g_barc[i], 0) < NBLK) __nanosleep(32);
        __threadfence();
    }
    __syncthreads();
}

// warp dot: out[t] = row_t(M) . v   (lane reads float4, 5-stage reduce)
__device__ __forceinline__ float warp_dot_row(const float* __restrict__ M,
                                              int t, const float4 vv, int lane) {
    float4 m = *(const float4*)(M + (size_t)t * D + lane * 4);
    float d = m.x * vv.x + m.y * vv.y + m.z * vv.z + m.w * vv.w;
    #pragma unroll
    for (int o = 16; o > 0; o >>= 1)
        d += __shfl_xor_sync(0xFFFFFFFFu, d, o);
    return d;
}

__global__ __launch_bounds__(NTHR, 1) void fused_kernel(
    const float* __restrict__ x,  const void* __restrict__ ei,
    const float* __restrict__ ew,
    const float* __restrict__ W1, const float* __restrict__ b1,
    const float* __restrict__ W2, const float* __restrict__ b2,
    const float* __restrict__ Wf, const float* __restrict__ bf,
    float* __restrict__ out)
{
    __shared__ unsigned int s_acc;

    const int tid  = threadIdx.x;
    const int bid  = blockIdx.x;
    const int gt   = bid * NTHR + tid;
    const int wid  = tid >> 5, lane = tid & 31;

    // ====== P0: detect (blk 0) | c2 (blk 1) | v2 = W2@Wf (blks 2-5) | zero (6+)
    if (bid == 0) {
        if (tid == 0) s_acc = 0u;
        __syncthreads();
        unsigned int v = ((const unsigned int*)ei)[2 * tid + 1];
        if (v) atomicOr(&s_acc, v);
        __syncthreads();
        if (tid == 0) g_is64 = (s_acc == 0u) ? 1 : 0;
    } else if (bid == 1) {
        if (wid == 0) {                              // c2 = b2.Wf + bf
            float4 a = *(const float4*)(b2 + lane * 4);
            float4 b = *(const float4*)(Wf + lane * 4);
            float d = a.x * b.x + a.y * b.y + a.z * b.z + a.w * b.w;
            #pragma unroll
            for (int o = 16; o > 0; o >>= 1)
                d += __shfl_xor_sync(0xFFFFFFFFu, d, o);
            if (lane == 0) g_c2 = d + bf[0];
        }
    } else if (bid < 6) {
        int t = (bid - 2) * 32 + wid;                // 128 outputs, warp each
        float4 wf4 = *(const float4*)(Wf + lane * 4);
        float d = warp_dot_row(W2, t, wf4, lane);
        if (lane == 0) g_v2[t] = d;
    } else {
        int base = (bid - 6) * NTHR + tid;
        for (int i = base; i < N_NODES; i += 142 * NTHR) {
            g_deg[i] = 0.0f; g_t1e[i] = 0.0f; g_ue[i] = 0.0f; g_t2e[i] = 0.0f;
        }
    }
    gbar(0);

    // ====== P0b: w = W1@v2 (blks 2-5) | c1 = b1.v2 (blk 1)
    if (bid == 1) {
        if (wid == 0) {
            float4 a = *(const float4*)(b1 + lane * 4);
            float4 b = __ldcg((const float4*)g_v2 + lane);
            float d = a.x * b.x + a.y * b.y + a.z * b.z + a.w * b.w;
            #pragma unroll
            for (int o = 16; o > 0; o >>= 1)
                d += __shfl_xor_sync(0xFFFFFFFFu, d, o);
            if (lane == 0) g_c1 = d;
        }
    } else if (bid >= 2 && bid < 6) {
        int t = (bid - 2) * 32 + wid;
        float4 v24 = __ldcg((const float4*)g_v2 + lane);
        float d = warp_dot_row(W1, t, v24, lane);
        if (lane == 0) g_w[t] = d;
    }
    gbar(1);

    // ====== P1: gemv y0 = X@w (2 rows in flight) + decode edges + deg atomics
    {
        int gwarp = gt >> 5;
        float4 wv4 = __ldcg((const float4*)g_w + lane);
        for (int n = gwarp; n < N_NODES; n += 2 * NW) {
            int n2 = n + NW;
            float4 a = *(const float4*)(x + (size_t)n * D + lane * 4);
            float d1 = a.x * wv4.x + a.y * wv4.y + a.z * wv4.z + a.w * wv4.w;
            float d2 = 0.0f;
            if (n2 < N_NODES) {
                float4 b = *(const float4*)(x + (size_t)n2 * D + lane * 4);
                d2 = b.x * wv4.x + b.y * wv4.y + b.z * wv4.z + b.w * wv4.w;
            }
            #pragma unroll
            for (int o = 16; o > 0; o >>= 1) {
                d1 += __shfl_xor_sync(0xFFFFFFFFu, d1, o);
                d2 += __shfl_xor_sync(0xFFFFFFFFu, d2, o);
            }
            if (lane == 0) {
                g_y0[n] = d1;
                if (n2 < N_NODES) g_y0[n2] = d2;
            }
        }
    }
    int es[EPT], ed[EPT];
    float eev[EPT];
    {
        int is64 = __ldcg(&g_is64);
        #pragma unroll
        for (int i = 0; i < EPT; i++) {
            int e = gt + i * NTOT;
            es[i] = 0; ed[i] = 0; eev[i] = 0.0f;
            if (e < N_EDGES) {
                int s, d;
                if (is64) {
                    const long long* p = (const long long*)ei;
                    s = (int)p[e]; d = (int)p[N_EDGES + e];
                } else {
                    const int* p = (const int*)ei;
                    s = p[e]; d = p[N_EDGES + e];
                }
                float w = ew[e];
                es[i] = s; ed[i] = d; eev[i] = w;
                atomicAdd(&g_deg[d], w);
            }
        }
    }
    gbar(2);

    // ====== P2: edge pass 1 — t1e[d] += nm*y0[s], ue[d] += nm
    float enm[EPT], edy[EPT];
    #pragma unroll
    for (int i = 0; i < EPT; i++) {
        int e = gt + i * NTOT;
        enm[i] = 0.0f; edy[i] = 0.0f;
        if (e < N_EDGES) {
            int s = es[i], d = ed[i];
            float dis = rsqrtf(__ldcg(&g_deg[s]) + 1.0f);
            float did = rsqrtf(__ldcg(&g_deg[d]) + 1.0f);
            float nm  = dis * eev[i] * did;
            float y0s = __ldcg(&g_y0[s]);
            enm[i] = nm;
            edy[i] = dis * dis * y0s;            // self part of t1_full[s]
            atomicAdd(&g_t1e[d], nm * y0s);
            atomicAdd(&g_ue[d], nm);
        }
    }
    gbar(3);

    // ====== P3: edge pass 2 — t2e[d] += nm * t1_full[s]
    #pragma unroll
    for (int i = 0; i < EPT; i++) {
        int e = gt + i * NTOT;
        if (e < N_EDGES) {
            float t1fs = edy[i] + __ldcg(&g_t1e[es[i]]);
            atomicAdd(&g_t2e[ed[i]], enm[i] * t1fs);
        }
    }
    gbar(4);

    // ====== P4: final head
    {
        float c1 = __ldcg(&g_c1), c2 = __ldcg(&g_c2);
        for (int n = gt; n < N_NODES; n += NTOT) {
            float di  = rsqrtf(__ldcg(&g_deg[n]) + 1.0f);
            float sl  = di * di;
            float y0  = __ldcg(&g_y0[n]);
            float t1f = sl * y0 + __ldcg(&g_t1e[n]);
            float uf  = sl + __ldcg(&g_ue[n]);
            float z   = sl * t1f + __ldcg(&g_t2e[n]) + c1 * uf + c2;
            out[n] = 10.0f / (1.0f + expf(-z));
        }
    }
}

// ================= launcher =================
extern "C" void kernel_launch(void* const* d_in, const int* in_sizes, int n_in,
                              void* d_out, int out_size) {
    const float* x  = (const float*)d_in[0];
    const void*  ei = d_in[1];
    const float* ew = (const float*)d_in[2];
    const float* W1 = (const float*)d_in[3];
    const float* b1 = (const float*)d_in[4];
    const float* W2 = (const float*)d_in[5];
    const float* b2 = (const float*)d_in[6];
    const float* Wf = (const float*)d_in[7];
    const float* bf = (const float*)d_in[8];
    float* out = (float*)d_out;

    reset_kernel<<<1, 32>>>();
    fused_kernel<<<NBLK, NTHR>>>(x, ei, ew, W1, b1, W2, b2, Wf, bf, out);
}

// round 12
// speedup vs baseline: 4.7592x; 1.0997x over previous
#include <cuda_runtime.h>
#include <cstdint>
#include <math.h>

#define N_NODES 50000
#define N_EDGES 500000
#define D 128
#define NBLK 148
#define NTHR 1024
#define NTOT (NBLK * NTHR)          // 151552 threads
#define NW   (NTOT / 32)            // 4736 warps
#define EPT 4                        // max edges per thread

// ---------------- device state ----------------
__device__ int   g_barc[4];          // arrive counters (self-resetting)
__device__ int   g_gen[4];           // release generations (monotonic)
__device__ float g_deg[N_NODES];
__device__ float g_y0[N_NODES];      // X @ w
__device__ float g_t1e[N_NODES];     // edge part of Anorm(y0)
__device__ float g_t2e[N_NODES];     // edge part of Anorm(t1 + c1)

// sense-reversing grid barrier: no host-side reset needed across replays
__device__ __forceinline__ void gbar(int i) {
    __syncthreads();
    if (threadIdx.x == 0) {
        int gen = __ldcg(&g_gen[i]);
        __threadfence();
        int ticket = atomicAdd(&g_barc[i], 1);
        if (ticket == NBLK - 1) {
            atomicExch(&g_barc[i], 0);       // reset for next replay
            __threadfence();
            atomicAdd(&g_gen[i], 1);         // release
        } else {
            while (__ldcg(&g_gen[i]) == gen) __nanosleep(20);
        }
        __threadfence();
    }
    __syncthreads();
}

// warp dot: row_t(M) . v, v held as per-lane float4
__device__ __forceinline__ float warp_dot_row(const float* __restrict__ M,
                                              int t, const float4 vv, int lane) {
    float4 m = *(const float4*)(M + (size_t)t * D + lane * 4);
    float d = m.x * vv.x + m.y * vv.y + m.z * vv.z + m.w * vv.w;
    #pragma unroll
    for (int o = 16; o > 0; o >>= 1)
        d += __shfl_xor_sync(0xFFFFFFFFu, d, o);
    return d;
}

__global__ __launch_bounds__(NTHR, 1) void fused_kernel(
    const float* __restrict__ x,  const void* __restrict__ ei,
    const float* __restrict__ ew,
    const float* __restrict__ W1, const float* __restrict__ b1,
    const float* __restrict__ W2, const float* __restrict__ b2,
    const float* __restrict__ Wf, const float* __restrict__ bf,
    float* __restrict__ out)
{
    __shared__ unsigned int s_acc;
    __shared__ __align__(16) float s_v2[D];
    __shared__ __align__(16) float s_w[D];
    __shared__ float s_c1, s_c2;

    const int tid  = threadIdx.x;
    const int bid  = blockIdx.x;
    const int gt   = bid * NTHR + tid;
    const int wid  = tid >> 5, lane = tid & 31;

    // ====== P0: zero accumulators | local is64 detect | decode edges to regs
    //        | per-block weight collapse (v2, w, c1, c2) in SMEM
    for (int i = gt; i < N_NODES; i += NTOT) {
        g_deg[i] = 0.0f; g_t1e[i] = 0.0f; g_t2e[i] = 0.0f;
    }
    // is64: odd 32-bit words of first 1024 int64 values are all zero
    if (tid == 0) s_acc = 0u;
    __syncthreads();
    {
        unsigned int v = ((const unsigned int*)ei)[2 * tid + 1];
        if (v) atomicOr(&s_acc, v);
    }
    // v2 = W2 @ Wf : 32 warps x 4 rows each
    {
        float4 wf4 = *(const float4*)(Wf + lane * 4);
        #pragma unroll
        for (int r = 0; r < 4; r++) {
            int t = wid * 4 + r;
            float d = warp_dot_row(W2, t, wf4, lane);
            if (lane == 0) s_v2[t] = d;
        }
    }
    __syncthreads();
    const int is64 = (s_acc == 0u) ? 1 : 0;
    // w = W1 @ v2 ; c1 = b1.v2 ; c2 = b2.Wf + bf
    {
        float4 v24 = *(const float4*)(s_v2 + lane * 4);
        #pragma unroll
        for (int r = 0; r < 4; r++) {
            int t = wid * 4 + r;
            float d = warp_dot_row(W1, t, v24, lane);
            if (lane == 0) s_w[t] = d;
        }
        if (wid == 0) {
            float4 a = *(const float4*)(b1 + lane * 4);
            float d = a.x * v24.x + a.y * v24.y + a.z * v24.z + a.w * v24.w;
            #pragma unroll
            for (int o = 16; o > 0; o >>= 1)
                d += __shfl_xor_sync(0xFFFFFFFFu, d, o);
            if (lane == 0) s_c1 = d;
        }
        if (wid == 1) {
            float4 a = *(const float4*)(b2 + lane * 4);
            float4 b = *(const float4*)(Wf + lane * 4);
            float d = a.x * b.x + a.y * b.y + a.z * b.z + a.w * b.w;
            #pragma unroll
            for (int o = 16; o > 0; o >>= 1)
                d += __shfl_xor_sync(0xFFFFFFFFu, d, o);
            if (lane == 0) s_c2 = d + bf[0];
        }
    }
    // decode edges into registers (overlaps with weight dots via ILP)
    int es[EPT], ed[EPT];
    float eev[EPT];
    #pragma unroll
    for (int i = 0; i < EPT; i++) {
        int e = gt + i * NTOT;
        es[i] = 0; ed[i] = 0; eev[i] = 0.0f;
        if (e < N_EDGES) {
            int s, d;
            if (is64) {
                const long long* p = (const long long*)ei;
                s = (int)p[e]; d = (int)p[N_EDGES + e];
            } else {
                const int* p = (const int*)ei;
                s = p[e]; d = p[N_EDGES + e];
            }
            es[i] = s; ed[i] = d; eev[i] = ew[e];
        }
    }
    gbar(0);

    // ====== P1: GEMV y0 = X@w (2 rows in flight) + deg atomics
    {
        int gwarp = gt >> 5;
        float4 wv4 = *(const float4*)(s_w + lane * 4);
        for (int n = gwarp; n < N_NODES; n += 2 * NW) {
            int n2 = n + NW;
            float4 a = *(const float4*)(x + (size_t)n * D + lane * 4);
            float d1 = a.x * wv4.x + a.y * wv4.y + a.z * wv4.z + a.w * wv4.w;
            float d2 = 0.0f;
            if (n2 < N_NODES) {
                float4 b = *(const float4*)(x + (size_t)n2 * D + lane * 4);
                d2 = b.x * wv4.x + b.y * wv4.y + b.z * wv4.z + b.w * wv4.w;
            }
            #pragma unroll
            for (int o = 16; o > 0; o >>= 1) {
                d1 += __shfl_xor_sync(0xFFFFFFFFu, d1, o);
                d2 += __shfl_xor_sync(0xFFFFFFFFu, d2, o);
            }
            if (lane == 0) {
                g_y0[n] = d1;
                if (n2 < N_NODES) g_y0[n2] = d2;
            }
        }
    }
    #pragma unroll
    for (int i = 0; i < EPT; i++) {
        int e = gt + i * NTOT;
        if (e < N_EDGES) atomicAdd(&g_deg[ed[i]], eev[i]);
    }
    gbar(1);

    // ====== P2: edge pass 1 — t1e[d] += nm*y0[s]
    float enm[EPT], edy[EPT];
    #pragma unroll
    for (int i = 0; i < EPT; i++) {
        int e = gt + i * NTOT;
        enm[i] = 0.0f; edy[i] = 0.0f;
        if (e < N_EDGES) {
            int s = es[i], d = ed[i];
            float dis = rsqrtf(__ldcg(&g_deg[s]) + 1.0f);
            float did = rsqrtf(__ldcg(&g_deg[d]) + 1.0f);
            float nm  = dis * eev[i] * did;
            float y0s = __ldcg(&g_y0[s]);
            enm[i] = nm;
            edy[i] = dis * dis * y0s;            // self part of t1_full[s]
            atomicAdd(&g_t1e[d], nm * y0s);
        }
    }
    gbar(2);

    // ====== P3: edge pass 2 — t2e[d] += nm * (t1_full[s] + c1)
    {
        float c1 = s_c1;
        #pragma unroll
        for (int i = 0; i < EPT; i++) {
            int e = gt + i * NTOT;
            if (e < N_EDGES) {
                float t1cs = edy[i] + __ldcg(&g_t1e[es[i]]) + c1;
                atomicAdd(&g_t2e[ed[i]], enm[i] * t1cs);
            }
        }
    }
    gbar(3);

    // ====== P4: z = sl*(t1f + c1) + t2e + c2 ; out = 10*sigmoid(z)
    {
        float c1 = s_c1, c2 = s_c2;
        for (int n = gt; n < N_NODES; n += NTOT) {
            float di  = rsqrtf(__ldcg(&g_deg[n]) + 1.0f);
            float sl  = di * di;
            float t1c = sl * __ldcg(&g_y0[n]) + __ldcg(&g_t1e[n]) + c1;
            float z   = sl * t1c + __ldcg(&g_t2e[n]) + c2;
            out[n] = 10.0f / (1.0f + expf(-z));
        }
    }
}

// ================= launcher =================
extern "C" void kernel_launch(void* const* d_in, const int* in_sizes, int n_in,
                              void* d_out, int out_size) {
    const float* x  = (const float*)d_in[0];
    const void*  ei = d_in[1];
    const float* ew = (const float*)d_in[2];
    const float* W1 = (const float*)d_in[3];
    const float* b1 = (const float*)d_in[4];
    const float* W2 = (const float*)d_in[5];
    const float* b2 = (const float*)d_in[6];
    const float* Wf = (const float*)d_in[7];
    const float* bf = (const float*)d_in[8];
    float* out = (float*)d_out;

    fused_kernel<<<NBLK, NTHR>>>(x, ei, ew, W1, b1, W2, b2, Wf, bf, out);
}